// round 13
// baseline (speedup 1.0000x reference)
#include <cuda_runtime.h>
#include <cuda_fp16.h>
#include <math.h>
#include <stdint.h>

#define Bb 4
#define Ss 2048
#define Dd 1024
#define Ff 4096

// ---------------- scratch (device globals; no runtime allocation) ----------------
__device__ __align__(1024) float g_scores[(long)Bb*Ss*Ss];
__device__ __align__(1024) float g_attn  [(long)Bb*Ss*Dd];   // holds x+attn after attn GEMM (EPI=4)
__device__ __align__(1024) float g_h     [(long)Bb*Ss*Dd];
__device__ __align__(1024) float g_ffn2  [(long)Bb*Ss*Dd];
__device__ __align__(1024) __half g_Xh [(long)Bb*Ss*Dd];
__device__ __align__(1024) __half g_XTh[(long)Bb*Dd*Ss];
__device__ __align__(1024) __half g_Ph [(long)Bb*Ss*Ss];
__device__ __align__(1024) __half g_Hh [(long)Bb*Ss*Dd];
__device__ __align__(1024) __half g_W1h[(long)Ff*Dd];
__device__ __align__(1024) __half g_W2h[(long)Dd*Ff];
__device__ __align__(1024) __half g_Fh [(long)Bb*Ss*Ff];

// ---------------- PTX helpers (baseline ISA only) ----------------
__device__ __forceinline__ uint32_t swz64(uint32_t o)  { return o ^ ((o >> 3) & 0x30); }

__device__ __forceinline__ void cp16(uint32_t s, const void* g) {
    asm volatile("cp.async.cg.shared.global [%0], [%1], 16;" :: "r"(s), "l"(g));
}

__device__ __forceinline__ void ldm4(uint32_t* r, uint32_t a) {
    asm volatile("ldmatrix.sync.aligned.m8n8.x4.shared.b16 {%0,%1,%2,%3}, [%4];"
        : "=r"(r[0]), "=r"(r[1]), "=r"(r[2]), "=r"(r[3]) : "r"(a));
}

__device__ __forceinline__ void mma16816(float* c, const uint32_t* a, const uint32_t* b) {
    asm volatile(
        "mma.sync.aligned.m16n8k16.row.col.f32.f16.f16.f32 "
        "{%0,%1,%2,%3},{%4,%5,%6,%7},{%8,%9},{%0,%1,%2,%3};"
        : "+f"(c[0]), "+f"(c[1]), "+f"(c[2]), "+f"(c[3])
        : "r"(a[0]), "r"(a[1]), "r"(a[2]), "r"(a[3]), "r"(b[0]), "r"(b[1]));
}

// ============================================================================
// SYM GEMM (scores): 128x128 CTA, 8 warps of 32x64, BK=32, 4 stages, occ 2
// ============================================================================
#define S_BM 128
#define S_BN 128
#define S_BK 32
#define S_NTH 256
#define S_STAGES 4
#define S_OFF_B (S_BM*64)
#define S_STAGE_BYTES (2*S_BM*64)                 // 16384
#define S_SMEM_SZ (128*132*4)                     // 67584 (mirror staging dominates)

__device__ __forceinline__ void s_load_stage(
    uint32_t sb, const __half* __restrict__ A, const __half* __restrict__ B,
    int tid, int m0, int n0, int K, int k0)
{
    const int row = tid >> 1;
    const int cb  = (tid & 1) * 32;
    const uint32_t so = (uint32_t)row * 64u + (uint32_t)cb;
    const char* ga = (const char*)(A + (long)(m0 + row) * K + k0) + cb;
    const char* gb = (const char*)(B + (long)(n0 + row) * K + k0) + cb;
    cp16(sb + swz64(so),              ga);
    cp16(sb + swz64(so + 16),         ga + 16);
    cp16(sb + S_OFF_B + swz64(so),    gb);
    cp16(sb + S_OFF_B + swz64(so+16), gb + 16);
}

__global__ __launch_bounds__(S_NTH, 2)
void gemm_sym(
    const __half* __restrict__ A, const __half* __restrict__ B,
    float* __restrict__ C, int N, int K, long sA, long sC,
    const float* __restrict__ aux, long sAux, float scale)
{
    const int m0 = blockIdx.y * S_BM, n0 = blockIdx.x * S_BN;
    if (m0 < n0) return;

    extern __shared__ char dsm[];
    const uint32_t data = (uint32_t)__cvta_generic_to_shared(dsm);

    const int tid = threadIdx.x, wid = tid >> 5, lane = tid & 31;
    const int wm = wid >> 1, wn = wid & 1;
    const int bz = blockIdx.z;
    A += bz * sA;
    B += bz * sA;

    float acc[2][8][4];
    #pragma unroll
    for (int i = 0; i < 2; i++)
        #pragma unroll
        for (int j = 0; j < 8; j++)
            #pragma unroll
            for (int q = 0; q < 4; q++) acc[i][j][q] = 0.f;

    const int nch = K / S_BK;
    s_load_stage(data, A, B, tid, m0, n0, K, 0);
    asm volatile("cp.async.commit_group;");
    s_load_stage(data + S_STAGE_BYTES, A, B, tid, m0, n0, K, S_BK);
    asm volatile("cp.async.commit_group;");
    s_load_stage(data + 2 * S_STAGE_BYTES, A, B, tid, m0, n0, K, 2 * S_BK);
    asm volatile("cp.async.commit_group;");

    int sidx = 0;
    for (int i = 0; i < nch; i++) {
        if (i + 3 <= nch)      asm volatile("cp.async.wait_group 2;");
        else if (i + 2 == nch) asm volatile("cp.async.wait_group 1;");
        else                   asm volatile("cp.async.wait_group 0;");
        __syncthreads();

        if (i + 3 < nch) {
            const int s2 = (i + 3) & (S_STAGES - 1);
            s_load_stage(data + (uint32_t)s2 * S_STAGE_BYTES, A, B, tid, m0, n0, K, (i + 3) * S_BK);
            asm volatile("cp.async.commit_group;");
        }

        const uint32_t sb = data + (uint32_t)sidx * S_STAGE_BYTES;
        sidx = (sidx + 1) & (S_STAGES - 1);

        uint32_t ah[2][2][4], bh[2][4][4];
        #pragma unroll
        for (int k16 = 0; k16 < 2; k16++) {
            const uint32_t arow = (uint32_t)(wm * 32 + (lane & 15));
            const uint32_t acol = (uint32_t)(k16 * 32 + (lane >> 4) * 16);
            ldm4(ah[k16][0], sb + swz64(arow * 64 + acol));
            ldm4(ah[k16][1], sb + swz64((arow + 16) * 64 + acol));
            const uint32_t brow = (uint32_t)(wn * 64 + (lane & 7) + (lane >> 4) * 8);
            const uint32_t bcol = (uint32_t)(k16 * 32 + ((lane >> 3) & 1) * 16);
            #pragma unroll
            for (int j = 0; j < 4; j++)
                ldm4(bh[k16][j], sb + S_OFF_B + swz64((brow + j * 16) * 64 + bcol));
        }
        #pragma unroll
        for (int k16 = 0; k16 < 2; k16++)
            #pragma unroll
            for (int mi = 0; mi < 2; mi++)
                #pragma unroll
                for (int nj = 0; nj < 8; nj++)
                    mma16816(acc[mi][nj], ah[k16][mi], &bh[k16][nj >> 1][(nj & 1) * 2]);
    }
    __syncthreads();

    const float* auxp = aux + bz * sAux;
    C += bz * sC;
    float* ts = (float*)dsm;

    #pragma unroll
    for (int mi = 0; mi < 2; mi++) {
        const int r0 = m0 + wm * 32 + mi * 16 + (lane >> 2);
        const float mr0 = __ldg(&auxp[r0]);
        const float mr8 = __ldg(&auxp[r0 + 8]);
        #pragma unroll
        for (int nj = 0; nj < 8; nj++) {
            const int c0 = n0 + wn * 64 + nj * 8 + (lane & 3) * 2;
            const float mc0 = __ldg(&auxp[c0]);
            const float mc1 = __ldg(&auxp[c0 + 1]);
            float raw[4];
            #pragma unroll
            for (int q = 0; q < 4; q++) raw[q] = acc[mi][nj][q] * scale;
            float2 lo; lo.x = raw[0] + mc0; lo.y = raw[1] + mc1;
            float2 hi; hi.x = raw[2] + mc0; hi.y = raw[3] + mc1;
            *reinterpret_cast<float2*>(C + (long)r0 * N + c0)       = lo;
            *reinterpret_cast<float2*>(C + (long)(r0 + 8) * N + c0) = hi;
            const int rl = wm * 32 + mi * 16 + (lane >> 2);
            const int cl = wn * 64 + nj * 8 + (lane & 3) * 2;
            ts[cl * 132 + rl]           = raw[0] + mr0;
            ts[(cl + 1) * 132 + rl]     = raw[1] + mr0;
            ts[cl * 132 + rl + 8]       = raw[2] + mr8;
            ts[(cl + 1) * 132 + rl + 8] = raw[3] + mr8;
        }
    }

    __syncthreads();
    #pragma unroll
    for (int it = tid; it < 128 * 32; it += S_NTH) {
        const int cc = it >> 5;
        const int q4 = it & 31;
        float4 vv = *reinterpret_cast<float4*>(&ts[cc * 132 + q4 * 4]);
        *reinterpret_cast<float4*>(C + (long)(n0 + cc) * N + m0 + q4 * 4) = vv;
    }
}

// ============================================================================
// General GEMM: 128x64 CTA, 8 warps of 32x32, BK=32, 4 stages, occ 4 (was 3)
// EPI: 2 gelu(acc+bias[col])->fp16, 3 acc+bias[col], 4 acc + res[row,col]
// ============================================================================
#define BM 128
#define BN 64
#define BK 32
#define NTH 256
#define STAGES 4
#define OFF_B (BM*64)
#define STAGE_BYTES ((BM+BN)*64)              // 12288
#define SMEM_SZ (STAGES*STAGE_BYTES)          // 49152

__device__ __forceinline__ void load_stage(
    uint32_t sb, const __half* __restrict__ A, const __half* __restrict__ B,
    int tid, int m0, int n0, int K, int k0)
{
    {
        const int row = tid >> 1;
        const int cb  = (tid & 1) * 32;
        const uint32_t so = (uint32_t)row * 64u + (uint32_t)cb;
        const char* ga = (const char*)(A + (long)(m0 + row) * K + k0) + cb;
        cp16(sb + swz64(so),      ga);
        cp16(sb + swz64(so + 16), ga + 16);
    }
    {
        const int row = tid >> 2;
        const int cb  = (tid & 3) * 16;
        const uint32_t so = (uint32_t)row * 64u + (uint32_t)cb;
        const char* gb = (const char*)(B + (long)(n0 + row) * K + k0) + cb;
        cp16(sb + OFF_B + swz64(so), gb);
    }
}

template<int EPI, bool HALF_OUT>
__global__ __launch_bounds__(NTH, 4)
void gemm_tc(
    const __half* __restrict__ A, const __half* __restrict__ B,
    float* __restrict__ C, __half* __restrict__ Ch,
    int N, int K, long sA, long sB, long sC,
    const float* __restrict__ aux, long sAux)
{
    const int m0 = blockIdx.y * BM, n0 = blockIdx.x * BN;

    extern __shared__ char dsm[];
    const uint32_t data = (uint32_t)__cvta_generic_to_shared(dsm);

    const int tid = threadIdx.x, wid = tid >> 5, lane = tid & 31;
    const int wm = wid >> 1, wn = wid & 1;
    const int bz = blockIdx.z;
    A += bz * sA;
    B += bz * sB;

    float acc[2][4][4];
    #pragma unroll
    for (int i = 0; i < 2; i++)
        #pragma unroll
        for (int j = 0; j < 4; j++)
            #pragma unroll
            for (int q = 0; q < 4; q++) acc[i][j][q] = 0.f;

    const int nch = K / BK;
    load_stage(data, A, B, tid, m0, n0, K, 0);
    asm volatile("cp.async.commit_group;");
    load_stage(data + STAGE_BYTES, A, B, tid, m0, n0, K, BK);
    asm volatile("cp.async.commit_group;");
    load_stage(data + 2 * STAGE_BYTES, A, B, tid, m0, n0, K, 2 * BK);
    asm volatile("cp.async.commit_group;");

    int sidx = 0;
    for (int i = 0; i < nch; i++) {
        if (i + 3 <= nch)      asm volatile("cp.async.wait_group 2;");
        else if (i + 2 == nch) asm volatile("cp.async.wait_group 1;");
        else                   asm volatile("cp.async.wait_group 0;");
        __syncthreads();

        if (i + 3 < nch) {
            const int s2 = (i + 3) & (STAGES - 1);
            load_stage(data + (uint32_t)s2 * STAGE_BYTES, A, B, tid, m0, n0, K, (i + 3) * BK);
            asm volatile("cp.async.commit_group;");
        }

        const uint32_t sb = data + (uint32_t)sidx * STAGE_BYTES;
        sidx = (sidx + 1) & (STAGES - 1);

        #pragma unroll
        for (int k16 = 0; k16 < 2; k16++) {
            uint32_t ah[2][4], bh[2][4];
            const uint32_t arow = (uint32_t)(wm * 32 + (lane & 15));
            const uint32_t acol = (uint32_t)(k16 * 32 + (lane >> 4) * 16);
            ldm4(ah[0], sb + swz64(arow * 64 + acol));
            ldm4(ah[1], sb + swz64((arow + 16) * 64 + acol));
            const uint32_t brow = (uint32_t)(wn * 32 + (lane & 7) + (lane >> 4) * 8);
            const uint32_t bcol = (uint32_t)(k16 * 32 + ((lane >> 3) & 1) * 16);
            ldm4(bh[0], sb + OFF_B + swz64(brow * 64 + bcol));
            ldm4(bh[1], sb + OFF_B + swz64((brow + 16) * 64 + bcol));

            #pragma unroll
            for (int mi = 0; mi < 2; mi++)
                #pragma unroll
                for (int nj = 0; nj < 4; nj++)
                    mma16816(acc[mi][nj], ah[mi], &bh[nj >> 1][(nj & 1) * 2]);
        }
    }

    // ---------------- epilogue ----------------
    const float* auxp = (EPI != 0) ? (aux + bz * sAux) : nullptr;
    if (!HALF_OUT && C) C += bz * sC;
    if (HALF_OUT) Ch += bz * sC;

    #pragma unroll
    for (int mi = 0; mi < 2; mi++) {
        const int r0 = m0 + wm * 32 + mi * 16 + (lane >> 2);
        #pragma unroll
        for (int nj = 0; nj < 4; nj++) {
            const int c0 = n0 + wn * 32 + nj * 8 + (lane & 3) * 2;
            float v[4] = { acc[mi][nj][0], acc[mi][nj][1], acc[mi][nj][2], acc[mi][nj][3] };
            if (EPI == 4) {
                float2 ra = *reinterpret_cast<const float2*>(auxp + (long)r0 * N + c0);
                float2 rb = *reinterpret_cast<const float2*>(auxp + (long)(r0 + 8) * N + c0);
                v[0] += ra.x; v[1] += ra.y; v[2] += rb.x; v[3] += rb.y;
            } else {
                #pragma unroll
                for (int q = 0; q < 4; q++) {
                    const int col = c0 + (q & 1);
                    float a = v[q];
                    if (EPI == 2)      { a += __ldg(&auxp[col]);
                                         a = 0.5f * a * (1.0f + erff(a * 0.70710678118654752f)); }
                    else if (EPI == 3) a += __ldg(&auxp[col]);
                    v[q] = a;
                }
            }
            if (!HALF_OUT) {
                float2 lo; lo.x = v[0]; lo.y = v[1];
                float2 hi; hi.x = v[2]; hi.y = v[3];
                *reinterpret_cast<float2*>(C + (long)r0 * N + c0)       = lo;
                *reinterpret_cast<float2*>(C + (long)(r0 + 8) * N + c0) = hi;
            } else {
                __half2 h01, h23;
                h01.x = __float2half_rn(v[0]); h01.y = __float2half_rn(v[1]);
                h23.x = __float2half_rn(v[2]); h23.y = __float2half_rn(v[3]);
                *reinterpret_cast<__half2*>(Ch + (long)r0 * N + c0)       = h01;
                *reinterpret_cast<__half2*>(Ch + (long)(r0 + 8) * N + c0) = h23;
            }
        }
    }
}

// ---------------- merged prep: x convert+transpose, w1 transpose, w2 transpose ----------------
// grid = 8192 (x) + 4096 (w1) + 4096 (w2) = 16384 blocks of 32x8
__global__ __launch_bounds__(256) void prep_kernel(
    const float* __restrict__ x, __half* __restrict__ Xh, __half* __restrict__ XTh,
    const float* __restrict__ w1, __half* __restrict__ W1h,
    const float* __restrict__ w2, __half* __restrict__ W2h)
{
    __shared__ float t[32][33];
    const int id = blockIdx.x;
    const int tx = threadIdx.x, ty = threadIdx.y;

    const float* in;
    __half* oht;
    __half* ohd = nullptr;
    int R, C, r0, c0;
    if (id < 8192) {
        const int bz  = id >> 11;
        const int rem = id & 2047;
        in  = x   + (long)bz * Ss * Dd;
        ohd = Xh  + (long)bz * Ss * Dd;
        oht = XTh + (long)bz * Dd * Ss;
        R = Ss; C = Dd;
        c0 = (rem & 31) * 32;      // over D
        r0 = (rem >> 5) * 32;      // over S
    } else if (id < 8192 + 4096) {
        const int rem = id - 8192;
        in = w1; oht = W1h;
        R = Dd; C = Ff;
        c0 = (rem & 127) * 32;     // over DFF
        r0 = (rem >> 7) * 32;      // over D
    } else {
        const int rem = id - 8192 - 4096;
        in = w2; oht = W2h;
        R = Ff; C = Dd;
        c0 = (rem & 31) * 32;      // over D
        r0 = (rem >> 5) * 32;      // over DFF
    }

    #pragma unroll
    for (int k = 0; k < 4; k++) {
        const float v = in[(long)(r0 + ty + 8*k) * C + c0 + tx];
        t[ty + 8*k][tx] = v;
        if (ohd) ohd[(long)(r0 + ty + 8*k) * C + c0 + tx] = __float2half_rn(v);
    }
    __syncthreads();
    #pragma unroll
    for (int k = 0; k < 4; k++) {
        const float v = t[tx][ty + 8*k];
        oht[(long)(c0 + ty + 8*k) * R + r0 + tx] = __float2half_rn(v);
    }
}

// ---------------- row softmax over S=2048 cols; register-resident, fp16 out ----------------
__global__ __launch_bounds__(256) void softmax_kernel(
    const float* __restrict__ s, __half* __restrict__ ph, int S)
{
    const long row = blockIdx.x;
    const float* p = s + row * (long)S;
    __half* oh = ph + row * (long)S;
    const int tid = threadIdx.x, lane = tid & 31, wrp = tid >> 5;
    __shared__ float red[8];

    float4 a = *reinterpret_cast<const float4*>(p + tid * 4);
    float4 b = *reinterpret_cast<const float4*>(p + 1024 + tid * 4);
    float v[8] = { a.x, a.y, a.z, a.w, b.x, b.y, b.z, b.w };

    float m = v[0];
    #pragma unroll
    for (int q = 1; q < 8; q++) m = fmaxf(m, v[q]);
    #pragma unroll
    for (int o = 16; o > 0; o >>= 1) m = fmaxf(m, __shfl_xor_sync(0xFFFFFFFF, m, o));
    if (lane == 0) red[wrp] = m;
    __syncthreads();
    m = red[0];
    #pragma unroll
    for (int w = 1; w < 8; w++) m = fmaxf(m, red[w]);

    float e[8], sum = 0.f;
    #pragma unroll
    for (int q = 0; q < 8; q++) { e[q] = expf(v[q] - m); sum += e[q]; }
    #pragma unroll
    for (int o = 16; o > 0; o >>= 1) sum += __shfl_xor_sync(0xFFFFFFFF, sum, o);
    __syncthreads();
    if (lane == 0) red[wrp] = sum;
    __syncthreads();
    sum = 0.f;
    #pragma unroll
    for (int w = 0; w < 8; w++) sum += red[w];
    const float inv = 1.f / sum;

    __half2 h0, h1, h2, h3;
    h0.x = __float2half_rn(e[0]*inv); h0.y = __float2half_rn(e[1]*inv);
    h1.x = __float2half_rn(e[2]*inv); h1.y = __float2half_rn(e[3]*inv);
    h2.x = __float2half_rn(e[4]*inv); h2.y = __float2half_rn(e[5]*inv);
    h3.x = __float2half_rn(e[6]*inv); h3.y = __float2half_rn(e[7]*inv);
    uint2 u0; u0.x = *reinterpret_cast<uint32_t*>(&h0); u0.y = *reinterpret_cast<uint32_t*>(&h1);
    uint2 u1; u1.x = *reinterpret_cast<uint32_t*>(&h2); u1.y = *reinterpret_cast<uint32_t*>(&h3);
    *reinterpret_cast<uint2*>(oh + tid * 4)        = u0;
    *reinterpret_cast<uint2*>(oh + 1024 + tid * 4) = u1;
}

// ---------------- LayerNorm (D=1024), float4, optional second input / fp16 out ----------------
template<bool TWO_IN, bool DO_HALF>
__global__ __launch_bounds__(256) void addln_kernel(
    const float* __restrict__ x, const float* __restrict__ y,
    const float* __restrict__ g, const float* __restrict__ b,
    float* __restrict__ out, __half* __restrict__ oh, int D)
{
    const long row = blockIdx.x;
    const int tid = threadIdx.x, lane = tid & 31, wrp = tid >> 5;
    const long base = row * (long)D + tid * 4;

    float4 xv = *reinterpret_cast<const float4*>(x + base);
    float v[4];
    if (TWO_IN) {
        float4 yv = *reinterpret_cast<const float4*>(y + base);
        v[0] = xv.x + yv.x; v[1] = xv.y + yv.y; v[2] = xv.z + yv.z; v[3] = xv.w + yv.w;
    } else {
        v[0] = xv.x; v[1] = xv.y; v[2] = xv.z; v[3] = xv.w;
    }

    float s = v[0] + v[1] + v[2] + v[3];
    float ss = v[0]*v[0] + v[1]*v[1] + v[2]*v[2] + v[3]*v[3];
    #pragma unroll
    for (int o = 16; o > 0; o >>= 1) {
        s  += __shfl_xor_sync(0xFFFFFFFF, s,  o);
        ss += __shfl_xor_sync(0xFFFFFFFF, ss, o);
    }
    __shared__ float r1[8], r2[8];
    if (lane == 0) { r1[wrp] = s; r2[wrp] = ss; }
    __syncthreads();
    s = 0.f; ss = 0.f;
    #pragma unroll
    for (int w = 0; w < 8; w++) { s += r1[w]; ss += r2[w]; }
    const float mean = s / (float)D;
    const float var  = ss / (float)D - mean * mean;
    const float rs   = rsqrtf(var + 1e-5f);

    float4 gv = *reinterpret_cast<const float4*>(g + tid * 4);
    float4 bv = *reinterpret_cast<const float4*>(b + tid * 4);
    float o0 = (v[0] - mean) * rs * gv.x + bv.x;
    float o1 = (v[1] - mean) * rs * gv.y + bv.y;
    float o2 = (v[2] - mean) * rs * gv.z + bv.z;
    float o3 = (v[3] - mean) * rs * gv.w + bv.w;
    float4 ov; ov.x = o0; ov.y = o1; ov.z = o2; ov.w = o3;
    *reinterpret_cast<float4*>(out + base) = ov;
    if (DO_HALF) {
        __half2 h01, h23;
        h01.x = __float2half_rn(o0); h01.y = __float2half_rn(o1);
        h23.x = __float2half_rn(o2); h23.y = __float2half_rn(o3);
        uint2 u; u.x = *reinterpret_cast<uint32_t*>(&h01); u.y = *reinterpret_cast<uint32_t*>(&h23);
        *reinterpret_cast<uint2*>(oh + base) = u;
    }
}

extern "C" void kernel_launch(void* const* d_in, const int* in_sizes, int n_in,
                              void* d_out, int out_size)
{
    const float* x    = (const float*)d_in[0];
    const float* mask = (const float*)d_in[1];
    const float* w1   = (const float*)d_in[2];
    const float* b1   = (const float*)d_in[3];
    const float* w2   = (const float*)d_in[4];
    const float* b2   = (const float*)d_in[5];
    const float* g1   = (const float*)d_in[6];
    const float* bt1  = (const float*)d_in[7];
    const float* g2   = (const float*)d_in[8];
    const float* bt2  = (const float*)d_in[9];
    float* out = (float*)d_out;

    float *scores, *attn, *h, *ffn2;
    __half *Xh, *XTh, *Ph, *Hh, *W1h, *W2h, *Fh;
    cudaGetSymbolAddress((void**)&scores, g_scores);
    cudaGetSymbolAddress((void**)&attn,   g_attn);
    cudaGetSymbolAddress((void**)&h,      g_h);
    cudaGetSymbolAddress((void**)&ffn2,   g_ffn2);
    cudaGetSymbolAddress((void**)&Xh,  g_Xh);
    cudaGetSymbolAddress((void**)&XTh, g_XTh);
    cudaGetSymbolAddress((void**)&Ph,  g_Ph);
    cudaGetSymbolAddress((void**)&Hh,  g_Hh);
    cudaGetSymbolAddress((void**)&W1h, g_W1h);
    cudaGetSymbolAddress((void**)&W2h, g_W2h);
    cudaGetSymbolAddress((void**)&Fh,  g_Fh);

    cudaFuncSetAttribute(gemm_sym,          cudaFuncAttributeMaxDynamicSharedMemorySize, S_SMEM_SZ);
    cudaFuncSetAttribute(gemm_tc<4,false>,  cudaFuncAttributeMaxDynamicSharedMemorySize, SMEM_SZ);
    cudaFuncSetAttribute(gemm_tc<2,true>,   cudaFuncAttributeMaxDynamicSharedMemorySize, SMEM_SZ);
    cudaFuncSetAttribute(gemm_tc<3,false>,  cudaFuncAttributeMaxDynamicSharedMemorySize, SMEM_SZ);

    const int B = Bb, S = Ss, D = Dd, DFF = Ff;
    const float scale = 0.03125f;  // 1/sqrt(1024)

    // 0) merged prep: x convert+transpose + both weight transposes in ONE launch
    prep_kernel<<<16384, dim3(32,8)>>>(x, Xh, XTh, w1, W1h, w2, W2h);

    // 1) scores = (X X^T) * scale + mask  (symmetric 128x128 tiles, mirrored via smem)
    gemm_sym<<<dim3(S/S_BN, S/S_BM, B), S_NTH, S_SMEM_SZ>>>(
        Xh, Xh, scores, S, D, (long)S*D, (long)S*S, mask, (long)S, scale);

    // 2) softmax rows -> P (fp16)
    softmax_kernel<<<B*S, 256>>>(scores, Ph, S);

    // 3) attn+x fused: attn_buf = P X + x   (EPI=4 residual add)
    gemm_tc<4,false><<<dim3(D/BN, S/BM, B), NTH, SMEM_SZ>>>(
        Ph, XTh, attn, nullptr, D, S, (long)S*S, (long)D*S, (long)S*D, x, (long)S*D);

    // 4) h = LN1(attn_buf)  (+ fp16 copy)
    addln_kernel<false,true><<<B*S, 256>>>(attn, nullptr, g1, bt1, h, Hh, D);

    // 5) F = gelu(h @ w1 + b1)  -> fp16 directly
    gemm_tc<2,true><<<dim3(DFF/BN, (B*S)/BM, 1), NTH, SMEM_SZ>>>(
        Hh, W1h, nullptr, Fh, DFF, D, 0, 0, 0, b1, 0);

    // 6) ffn2 = F @ w2 + b2 -> fp32
    gemm_tc<3,false><<<dim3(D/BN, (B*S)/BM, 1), NTH, SMEM_SZ>>>(
        Fh, W2h, ffn2, nullptr, D, DFF, 0, 0, 0, b2, 0);

    // 7) out = LN2(h + ffn2)
    addln_kernel<true,false><<<B*S, 256>>>(h, ffn2, g2, bt2, out, nullptr, D);
}

// round 14
// speedup vs baseline: 1.0323x; 1.0323x over previous
#include <cuda_runtime.h>
#include <cuda_fp16.h>
#include <math.h>
#include <stdint.h>

#define Bb 4
#define Ss 2048
#define Dd 1024
#define Ff 4096

// ---------------- scratch (device globals; no runtime allocation) ----------------
__device__ __align__(1024) float g_scores[(long)Bb*Ss*Ss];
__device__ __align__(1024) float g_attn  [(long)Bb*Ss*Dd];   // holds x+attn after attn GEMM (EPI=4)
__device__ __align__(1024) float g_h     [(long)Bb*Ss*Dd];
__device__ __align__(1024) float g_ffn2  [(long)Bb*Ss*Dd];
__device__ __align__(1024) __half g_Xh [(long)Bb*Ss*Dd];
__device__ __align__(1024) __half g_XTh[(long)Bb*Dd*Ss];
__device__ __align__(1024) __half g_Ph [(long)Bb*Ss*Ss];
__device__ __align__(1024) __half g_Hh [(long)Bb*Ss*Dd];
__device__ __align__(1024) __half g_W1h[(long)Ff*Dd];
__device__ __align__(1024) __half g_W2h[(long)Dd*Ff];
__device__ __align__(1024) __half g_Fh [(long)Bb*Ss*Ff];

// ---------------- PTX helpers (baseline ISA only) ----------------
__device__ __forceinline__ uint32_t swz64(uint32_t o)  { return o ^ ((o >> 3) & 0x30); }

__device__ __forceinline__ void cp16(uint32_t s, const void* g) {
    asm volatile("cp.async.cg.shared.global [%0], [%1], 16;" :: "r"(s), "l"(g));
}

__device__ __forceinline__ void ldm4(uint32_t* r, uint32_t a) {
    asm volatile("ldmatrix.sync.aligned.m8n8.x4.shared.b16 {%0,%1,%2,%3}, [%4];"
        : "=r"(r[0]), "=r"(r[1]), "=r"(r[2]), "=r"(r[3]) : "r"(a));
}

__device__ __forceinline__ void mma16816(float* c, const uint32_t* a, const uint32_t* b) {
    asm volatile(
        "mma.sync.aligned.m16n8k16.row.col.f32.f16.f16.f32 "
        "{%0,%1,%2,%3},{%4,%5,%6,%7},{%8,%9},{%0,%1,%2,%3};"
        : "+f"(c[0]), "+f"(c[1]), "+f"(c[2]), "+f"(c[3])
        : "r"(a[0]), "r"(a[1]), "r"(a[2]), "r"(a[3]), "r"(b[0]), "r"(b[1]));
}

// ============================================================================
// SYM GEMM (scores): 128x128 CTA, 8 warps of 32x64, BK=32, 4 stages, occ 2
// ============================================================================
#define S_BM 128
#define S_BN 128
#define S_BK 32
#define S_NTH 256
#define S_STAGES 4
#define S_OFF_B (S_BM*64)
#define S_STAGE_BYTES (2*S_BM*64)                 // 16384
#define S_SMEM_SZ (128*132*4)                     // 67584 (mirror staging dominates)

__device__ __forceinline__ void s_load_stage(
    uint32_t sb, const __half* __restrict__ A, const __half* __restrict__ B,
    int tid, int m0, int n0, int K, int k0)
{
    const int row = tid >> 1;
    const int cb  = (tid & 1) * 32;
    const uint32_t so = (uint32_t)row * 64u + (uint32_t)cb;
    const char* ga = (const char*)(A + (long)(m0 + row) * K + k0) + cb;
    const char* gb = (const char*)(B + (long)(n0 + row) * K + k0) + cb;
    cp16(sb + swz64(so),              ga);
    cp16(sb + swz64(so + 16),         ga + 16);
    cp16(sb + S_OFF_B + swz64(so),    gb);
    cp16(sb + S_OFF_B + swz64(so+16), gb + 16);
}

__global__ __launch_bounds__(S_NTH, 2)
void gemm_sym(
    const __half* __restrict__ A, const __half* __restrict__ B,
    float* __restrict__ C, int N, int K, long sA, long sC,
    const float* __restrict__ aux, long sAux, float scale)
{
    const int m0 = blockIdx.y * S_BM, n0 = blockIdx.x * S_BN;
    if (m0 < n0) return;

    extern __shared__ char dsm[];
    const uint32_t data = (uint32_t)__cvta_generic_to_shared(dsm);

    const int tid = threadIdx.x, wid = tid >> 5, lane = tid & 31;
    const int wm = wid >> 1, wn = wid & 1;
    const int bz = blockIdx.z;
    A += bz * sA;
    B += bz * sA;

    float acc[2][8][4];
    #pragma unroll
    for (int i = 0; i < 2; i++)
        #pragma unroll
        for (int j = 0; j < 8; j++)
            #pragma unroll
            for (int q = 0; q < 4; q++) acc[i][j][q] = 0.f;

    const int nch = K / S_BK;
    s_load_stage(data, A, B, tid, m0, n0, K, 0);
    asm volatile("cp.async.commit_group;");
    s_load_stage(data + S_STAGE_BYTES, A, B, tid, m0, n0, K, S_BK);
    asm volatile("cp.async.commit_group;");
    s_load_stage(data + 2 * S_STAGE_BYTES, A, B, tid, m0, n0, K, 2 * S_BK);
    asm volatile("cp.async.commit_group;");

    int sidx = 0;
    for (int i = 0; i < nch; i++) {
        if (i + 3 <= nch)      asm volatile("cp.async.wait_group 2;");
        else if (i + 2 == nch) asm volatile("cp.async.wait_group 1;");
        else                   asm volatile("cp.async.wait_group 0;");
        __syncthreads();

        if (i + 3 < nch) {
            const int s2 = (i + 3) & (S_STAGES - 1);
            s_load_stage(data + (uint32_t)s2 * S_STAGE_BYTES, A, B, tid, m0, n0, K, (i + 3) * S_BK);
            asm volatile("cp.async.commit_group;");
        }

        const uint32_t sb = data + (uint32_t)sidx * S_STAGE_BYTES;
        sidx = (sidx + 1) & (S_STAGES - 1);

        uint32_t ah[2][2][4], bh[2][4][4];
        #pragma unroll
        for (int k16 = 0; k16 < 2; k16++) {
            const uint32_t arow = (uint32_t)(wm * 32 + (lane & 15));
            const uint32_t acol = (uint32_t)(k16 * 32 + (lane >> 4) * 16);
            ldm4(ah[k16][0], sb + swz64(arow * 64 + acol));
            ldm4(ah[k16][1], sb + swz64((arow + 16) * 64 + acol));
            const uint32_t brow = (uint32_t)(wn * 64 + (lane & 7) + (lane >> 4) * 8);
            const uint32_t bcol = (uint32_t)(k16 * 32 + ((lane >> 3) & 1) * 16);
            #pragma unroll
            for (int j = 0; j < 4; j++)
                ldm4(bh[k16][j], sb + S_OFF_B + swz64((brow + j * 16) * 64 + bcol));
        }
        #pragma unroll
        for (int k16 = 0; k16 < 2; k16++)
            #pragma unroll
            for (int mi = 0; mi < 2; mi++)
                #pragma unroll
                for (int nj = 0; nj < 8; nj++)
                    mma16816(acc[mi][nj], ah[k16][mi], &bh[k16][nj >> 1][(nj & 1) * 2]);
    }
    __syncthreads();

    const float* auxp = aux + bz * sAux;
    C += bz * sC;
    float* ts = (float*)dsm;

    #pragma unroll
    for (int mi = 0; mi < 2; mi++) {
        const int r0 = m0 + wm * 32 + mi * 16 + (lane >> 2);
        const float mr0 = __ldg(&auxp[r0]);
        const float mr8 = __ldg(&auxp[r0 + 8]);
        #pragma unroll
        for (int nj = 0; nj < 8; nj++) {
            const int c0 = n0 + wn * 64 + nj * 8 + (lane & 3) * 2;
            const float mc0 = __ldg(&auxp[c0]);
            const float mc1 = __ldg(&auxp[c0 + 1]);
            float raw[4];
            #pragma unroll
            for (int q = 0; q < 4; q++) raw[q] = acc[mi][nj][q] * scale;
            float2 lo; lo.x = raw[0] + mc0; lo.y = raw[1] + mc1;
            float2 hi; hi.x = raw[2] + mc0; hi.y = raw[3] + mc1;
            *reinterpret_cast<float2*>(C + (long)r0 * N + c0)       = lo;
            *reinterpret_cast<float2*>(C + (long)(r0 + 8) * N + c0) = hi;
            const int rl = wm * 32 + mi * 16 + (lane >> 2);
            const int cl = wn * 64 + nj * 8 + (lane & 3) * 2;
            ts[cl * 132 + rl]           = raw[0] + mr0;
            ts[(cl + 1) * 132 + rl]     = raw[1] + mr0;
            ts[cl * 132 + rl + 8]       = raw[2] + mr8;
            ts[(cl + 1) * 132 + rl + 8] = raw[3] + mr8;
        }
    }

    __syncthreads();
    #pragma unroll
    for (int it = tid; it < 128 * 32; it += S_NTH) {
        const int cc = it >> 5;
        const int q4 = it & 31;
        float4 vv = *reinterpret_cast<float4*>(&ts[cc * 132 + q4 * 4]);
        *reinterpret_cast<float4*>(C + (long)(n0 + cc) * N + m0 + q4 * 4) = vv;
    }
}

// ============================================================================
// General GEMM (measured best): 128x64 CTA, 8 warps of 32x32, BK=32, 4 stages, occ 3
// EPI: 2 gelu(acc+bias[col])->fp16, 3 acc+bias[col], 4 acc + res[row,col]
// ============================================================================
#define BM 128
#define BN 64
#define BK 32
#define NTH 256
#define STAGES 4
#define OFF_B (BM*64)
#define STAGE_BYTES ((BM+BN)*64)              // 12288
#define SMEM_SZ (STAGES*STAGE_BYTES)          // 49152

__device__ __forceinline__ void load_stage(
    uint32_t sb, const __half* __restrict__ A, const __half* __restrict__ B,
    int tid, int m0, int n0, int K, int k0)
{
    {
        const int row = tid >> 1;
        const int cb  = (tid & 1) * 32;
        const uint32_t so = (uint32_t)row * 64u + (uint32_t)cb;
        const char* ga = (const char*)(A + (long)(m0 + row) * K + k0) + cb;
        cp16(sb + swz64(so),      ga);
        cp16(sb + swz64(so + 16), ga + 16);
    }
    {
        const int row = tid >> 2;
        const int cb  = (tid & 3) * 16;
        const uint32_t so = (uint32_t)row * 64u + (uint32_t)cb;
        const char* gb = (const char*)(B + (long)(n0 + row) * K + k0) + cb;
        cp16(sb + OFF_B + swz64(so), gb);
    }
}

template<int EPI, bool HALF_OUT>
__global__ __launch_bounds__(NTH, 3)
void gemm_tc(
    const __half* __restrict__ A, const __half* __restrict__ B,
    float* __restrict__ C, __half* __restrict__ Ch,
    int N, int K, long sA, long sB, long sC,
    const float* __restrict__ aux, long sAux)
{
    const int m0 = blockIdx.y * BM, n0 = blockIdx.x * BN;

    extern __shared__ char dsm[];
    const uint32_t data = (uint32_t)__cvta_generic_to_shared(dsm);

    const int tid = threadIdx.x, wid = tid >> 5, lane = tid & 31;
    const int wm = wid >> 1, wn = wid & 1;
    const int bz = blockIdx.z;
    A += bz * sA;
    B += bz * sB;

    float acc[2][4][4];
    #pragma unroll
    for (int i = 0; i < 2; i++)
        #pragma unroll
        for (int j = 0; j < 4; j++)
            #pragma unroll
            for (int q = 0; q < 4; q++) acc[i][j][q] = 0.f;

    const int nch = K / BK;
    load_stage(data, A, B, tid, m0, n0, K, 0);
    asm volatile("cp.async.commit_group;");
    load_stage(data + STAGE_BYTES, A, B, tid, m0, n0, K, BK);
    asm volatile("cp.async.commit_group;");
    load_stage(data + 2 * STAGE_BYTES, A, B, tid, m0, n0, K, 2 * BK);
    asm volatile("cp.async.commit_group;");

    int sidx = 0;
    for (int i = 0; i < nch; i++) {
        if (i + 3 <= nch)      asm volatile("cp.async.wait_group 2;");
        else if (i + 2 == nch) asm volatile("cp.async.wait_group 1;");
        else                   asm volatile("cp.async.wait_group 0;");
        __syncthreads();

        if (i + 3 < nch) {
            const int s2 = (i + 3) & (STAGES - 1);
            load_stage(data + (uint32_t)s2 * STAGE_BYTES, A, B, tid, m0, n0, K, (i + 3) * BK);
            asm volatile("cp.async.commit_group;");
        }

        const uint32_t sb = data + (uint32_t)sidx * STAGE_BYTES;
        sidx = (sidx + 1) & (STAGES - 1);

        #pragma unroll
        for (int k16 = 0; k16 < 2; k16++) {
            uint32_t ah[2][4], bh[2][4];
            const uint32_t arow = (uint32_t)(wm * 32 + (lane & 15));
            const uint32_t acol = (uint32_t)(k16 * 32 + (lane >> 4) * 16);
            ldm4(ah[0], sb + swz64(arow * 64 + acol));
            ldm4(ah[1], sb + swz64((arow + 16) * 64 + acol));
            const uint32_t brow = (uint32_t)(wn * 32 + (lane & 7) + (lane >> 4) * 8);
            const uint32_t bcol = (uint32_t)(k16 * 32 + ((lane >> 3) & 1) * 16);
            ldm4(bh[0], sb + OFF_B + swz64(brow * 64 + bcol));
            ldm4(bh[1], sb + OFF_B + swz64((brow + 16) * 64 + bcol));

            #pragma unroll
            for (int mi = 0; mi < 2; mi++)
                #pragma unroll
                for (int nj = 0; nj < 4; nj++)
                    mma16816(acc[mi][nj], ah[mi], &bh[nj >> 1][(nj & 1) * 2]);
        }
    }

    // ---------------- epilogue ----------------
    const float* auxp = (EPI != 0) ? (aux + bz * sAux) : nullptr;
    if (!HALF_OUT && C) C += bz * sC;
    if (HALF_OUT) Ch += bz * sC;

    #pragma unroll
    for (int mi = 0; mi < 2; mi++) {
        const int r0 = m0 + wm * 32 + mi * 16 + (lane >> 2);
        #pragma unroll
        for (int nj = 0; nj < 4; nj++) {
            const int c0 = n0 + wn * 32 + nj * 8 + (lane & 3) * 2;
            float v[4] = { acc[mi][nj][0], acc[mi][nj][1], acc[mi][nj][2], acc[mi][nj][3] };
            if (EPI == 4) {
                float2 ra = *reinterpret_cast<const float2*>(auxp + (long)r0 * N + c0);
                float2 rb = *reinterpret_cast<const float2*>(auxp + (long)(r0 + 8) * N + c0);
                v[0] += ra.x; v[1] += ra.y; v[2] += rb.x; v[3] += rb.y;
            } else {
                #pragma unroll
                for (int q = 0; q < 4; q++) {
                    const int col = c0 + (q & 1);
                    float a = v[q];
                    if (EPI == 2)      { a += __ldg(&auxp[col]);
                                         a = 0.5f * a * (1.0f + erff(a * 0.70710678118654752f)); }
                    else if (EPI == 3) a += __ldg(&auxp[col]);
                    v[q] = a;
                }
            }
            if (!HALF_OUT) {
                float2 lo; lo.x = v[0]; lo.y = v[1];
                float2 hi; hi.x = v[2]; hi.y = v[3];
                *reinterpret_cast<float2*>(C + (long)r0 * N + c0)       = lo;
                *reinterpret_cast<float2*>(C + (long)(r0 + 8) * N + c0) = hi;
            } else {
                __half2 h01, h23;
                h01.x = __float2half_rn(v[0]); h01.y = __float2half_rn(v[1]);
                h23.x = __float2half_rn(v[2]); h23.y = __float2half_rn(v[3]);
                *reinterpret_cast<__half2*>(Ch + (long)r0 * N + c0)       = h01;
                *reinterpret_cast<__half2*>(Ch + (long)(r0 + 8) * N + c0) = h23;
            }
        }
    }
}

// ---------------- merged prep: x convert+transpose, w1 transpose, w2 transpose ----------------
// grid = 8192 (x) + 4096 (w1) + 4096 (w2) = 16384 blocks of 32x8
__global__ __launch_bounds__(256) void prep_kernel(
    const float* __restrict__ x, __half* __restrict__ Xh, __half* __restrict__ XTh,
    const float* __restrict__ w1, __half* __restrict__ W1h,
    const float* __restrict__ w2, __half* __restrict__ W2h)
{
    __shared__ float t[32][33];
    const int id = blockIdx.x;
    const int tx = threadIdx.x, ty = threadIdx.y;

    const float* in;
    __half* oht;
    __half* ohd = nullptr;
    int R, C, r0, c0;
    if (id < 8192) {
        const int bz  = id >> 11;
        const int rem = id & 2047;
        in  = x   + (long)bz * Ss * Dd;
        ohd = Xh  + (long)bz * Ss * Dd;
        oht = XTh + (long)bz * Dd * Ss;
        R = Ss; C = Dd;
        c0 = (rem & 31) * 32;
        r0 = (rem >> 5) * 32;
    } else if (id < 8192 + 4096) {
        const int rem = id - 8192;
        in = w1; oht = W1h;
        R = Dd; C = Ff;
        c0 = (rem & 127) * 32;
        r0 = (rem >> 7) * 32;
    } else {
        const int rem = id - 8192 - 4096;
        in = w2; oht = W2h;
        R = Ff; C = Dd;
        c0 = (rem & 31) * 32;
        r0 = (rem >> 5) * 32;
    }

    #pragma unroll
    for (int k = 0; k < 4; k++) {
        const float v = in[(long)(r0 + ty + 8*k) * C + c0 + tx];
        t[ty + 8*k][tx] = v;
        if (ohd) ohd[(long)(r0 + ty + 8*k) * C + c0 + tx] = __float2half_rn(v);
    }
    __syncthreads();
    #pragma unroll
    for (int k = 0; k < 4; k++) {
        const float v = t[tx][ty + 8*k];
        oht[(long)(c0 + ty + 8*k) * R + r0 + tx] = __float2half_rn(v);
    }
}

// ---------------- row softmax over S=2048 cols; register-resident, fp16 out ----------------
__global__ __launch_bounds__(256) void softmax_kernel(
    const float* __restrict__ s, __half* __restrict__ ph, int S)
{
    const long row = blockIdx.x;
    const float* p = s + row * (long)S;
    __half* oh = ph + row * (long)S;
    const int tid = threadIdx.x, lane = tid & 31, wrp = tid >> 5;
    __shared__ float red[8];

    float4 a = *reinterpret_cast<const float4*>(p + tid * 4);
    float4 b = *reinterpret_cast<const float4*>(p + 1024 + tid * 4);
    float v[8] = { a.x, a.y, a.z, a.w, b.x, b.y, b.z, b.w };

    float m = v[0];
    #pragma unroll
    for (int q = 1; q < 8; q++) m = fmaxf(m, v[q]);
    #pragma unroll
    for (int o = 16; o > 0; o >>= 1) m = fmaxf(m, __shfl_xor_sync(0xFFFFFFFF, m, o));
    if (lane == 0) red[wrp] = m;
    __syncthreads();
    m = red[0];
    #pragma unroll
    for (int w = 1; w < 8; w++) m = fmaxf(m, red[w]);

    float e[8], sum = 0.f;
    #pragma unroll
    for (int q = 0; q < 8; q++) { e[q] = expf(v[q] - m); sum += e[q]; }
    #pragma unroll
    for (int o = 16; o > 0; o >>= 1) sum += __shfl_xor_sync(0xFFFFFFFF, sum, o);
    __syncthreads();
    if (lane == 0) red[wrp] = sum;
    __syncthreads();
    sum = 0.f;
    #pragma unroll
    for (int w = 0; w < 8; w++) sum += red[w];
    const float inv = 1.f / sum;

    __half2 h0, h1, h2, h3;
    h0.x = __float2half_rn(e[0]*inv); h0.y = __float2half_rn(e[1]*inv);
    h1.x = __float2half_rn(e[2]*inv); h1.y = __float2half_rn(e[3]*inv);
    h2.x = __float2half_rn(e[4]*inv); h2.y = __float2half_rn(e[5]*inv);
    h3.x = __float2half_rn(e[6]*inv); h3.y = __float2half_rn(e[7]*inv);
    uint2 u0; u0.x = *reinterpret_cast<uint32_t*>(&h0); u0.y = *reinterpret_cast<uint32_t*>(&h1);
    uint2 u1; u1.x = *reinterpret_cast<uint32_t*>(&h2); u1.y = *reinterpret_cast<uint32_t*>(&h3);
    *reinterpret_cast<uint2*>(oh + tid * 4)        = u0;
    *reinterpret_cast<uint2*>(oh + 1024 + tid * 4) = u1;
}

// ---------------- LayerNorm (D=1024), float4, optional second input / fp16 out ----------------
template<bool TWO_IN, bool DO_HALF>
__global__ __launch_bounds__(256) void addln_kernel(
    const float* __restrict__ x, const float* __restrict__ y,
    const float* __restrict__ g, const float* __restrict__ b,
    float* __restrict__ out, __half* __restrict__ oh, int D)
{
    const long row = blockIdx.x;
    const int tid = threadIdx.x, lane = tid & 31, wrp = tid >> 5;
    const long base = row * (long)D + tid * 4;

    float4 xv = *reinterpret_cast<const float4*>(x + base);
    float v[4];
    if (TWO_IN) {
        float4 yv = *reinterpret_cast<const float4*>(y + base);
        v[0] = xv.x + yv.x; v[1] = xv.y + yv.y; v[2] = xv.z + yv.z; v[3] = xv.w + yv.w;
    } else {
        v[0] = xv.x; v[1] = xv.y; v[2] = xv.z; v[3] = xv.w;
    }

    float s = v[0] + v[1] + v[2] + v[3];
    float ss = v[0]*v[0] + v[1]*v[1] + v[2]*v[2] + v[3]*v[3];
    #pragma unroll
    for (int o = 16; o > 0; o >>= 1) {
        s  += __shfl_xor_sync(0xFFFFFFFF, s,  o);
        ss += __shfl_xor_sync(0xFFFFFFFF, ss, o);
    }
    __shared__ float r1[8], r2[8];
    if (lane == 0) { r1[wrp] = s; r2[wrp] = ss; }
    __syncthreads();
    s = 0.f; ss = 0.f;
    #pragma unroll
    for (int w = 0; w < 8; w++) { s += r1[w]; ss += r2[w]; }
    const float mean = s / (float)D;
    const float var  = ss / (float)D - mean * mean;
    const float rs   = rsqrtf(var + 1e-5f);

    float4 gv = *reinterpret_cast<const float4*>(g + tid * 4);
    float4 bv = *reinterpret_cast<const float4*>(b + tid * 4);
    float o0 = (v[0] - mean) * rs * gv.x + bv.x;
    float o1 = (v[1] - mean) * rs * gv.y + bv.y;
    float o2 = (v[2] - mean) * rs * gv.z + bv.z;
    float o3 = (v[3] - mean) * rs * gv.w + bv.w;
    float4 ov; ov.x = o0; ov.y = o1; ov.z = o2; ov.w = o3;
    *reinterpret_cast<float4*>(out + base) = ov;
    if (DO_HALF) {
        __half2 h01, h23;
        h01.x = __float2half_rn(o0); h01.y = __float2half_rn(o1);
        h23.x = __float2half_rn(o2); h23.y = __float2half_rn(o3);
        uint2 u; u.x = *reinterpret_cast<uint32_t*>(&h01); u.y = *reinterpret_cast<uint32_t*>(&h23);
        *reinterpret_cast<uint2*>(oh + base) = u;
    }
}

extern "C" void kernel_launch(void* const* d_in, const int* in_sizes, int n_in,
                              void* d_out, int out_size)
{
    const float* x    = (const float*)d_in[0];
    const float* mask = (const float*)d_in[1];
    const float* w1   = (const float*)d_in[2];
    const float* b1   = (const float*)d_in[3];
    const float* w2   = (const float*)d_in[4];
    const float* b2   = (const float*)d_in[5];
    const float* g1   = (const float*)d_in[6];
    const float* bt1  = (const float*)d_in[7];
    const float* g2   = (const float*)d_in[8];
    const float* bt2  = (const float*)d_in[9];
    float* out = (float*)d_out;

    float *scores, *attn, *h, *ffn2;
    __half *Xh, *XTh, *Ph, *Hh, *W1h, *W2h, *Fh;
    cudaGetSymbolAddress((void**)&scores, g_scores);
    cudaGetSymbolAddress((void**)&attn,   g_attn);
    cudaGetSymbolAddress((void**)&h,      g_h);
    cudaGetSymbolAddress((void**)&ffn2,   g_ffn2);
    cudaGetSymbolAddress((void**)&Xh,  g_Xh);
    cudaGetSymbolAddress((void**)&XTh, g_XTh);
    cudaGetSymbolAddress((void**)&Ph,  g_Ph);
    cudaGetSymbolAddress((void**)&Hh,  g_Hh);
    cudaGetSymbolAddress((void**)&W1h, g_W1h);
    cudaGetSymbolAddress((void**)&W2h, g_W2h);
    cudaGetSymbolAddress((void**)&Fh,  g_Fh);

    cudaFuncSetAttribute(gemm_sym,          cudaFuncAttributeMaxDynamicSharedMemorySize, S_SMEM_SZ);
    cudaFuncSetAttribute(gemm_tc<4,false>,  cudaFuncAttributeMaxDynamicSharedMemorySize, SMEM_SZ);
    cudaFuncSetAttribute(gemm_tc<2,true>,   cudaFuncAttributeMaxDynamicSharedMemorySize, SMEM_SZ);
    cudaFuncSetAttribute(gemm_tc<3,false>,  cudaFuncAttributeMaxDynamicSharedMemorySize, SMEM_SZ);

    const int B = Bb, S = Ss, D = Dd, DFF = Ff;
    const float scale = 0.03125f;  // 1/sqrt(1024)

    // 0) merged prep: x convert+transpose + both weight transposes in ONE launch
    prep_kernel<<<16384, dim3(32,8)>>>(x, Xh, XTh, w1, W1h, w2, W2h);

    // 1) scores = (X X^T) * scale + mask  (symmetric 128x128 tiles, mirrored via smem)
    gemm_sym<<<dim3(S/S_BN, S/S_BM, B), S_NTH, S_SMEM_SZ>>>(
        Xh, Xh, scores, S, D, (long)S*D, (long)S*S, mask, (long)S, scale);

    // 2) softmax rows -> P (fp16)
    softmax_kernel<<<B*S, 256>>>(scores, Ph, S);

    // 3) attn+x fused: attn_buf = P X + x   (EPI=4 residual add)
    gemm_tc<4,false><<<dim3(D/BN, S/BM, B), NTH, SMEM_SZ>>>(
        Ph, XTh, attn, nullptr, D, S, (long)S*S, (long)D*S, (long)S*D, x, (long)S*D);

    // 4) h = LN1(attn_buf)  (+ fp16 copy)
    addln_kernel<false,true><<<B*S, 256>>>(attn, nullptr, g1, bt1, h, Hh, D);

    // 5) F = gelu(h @ w1 + b1)  -> fp16 directly
    gemm_tc<2,true><<<dim3(DFF/BN, (B*S)/BM, 1), NTH, SMEM_SZ>>>(
        Hh, W1h, nullptr, Fh, DFF, D, 0, 0, 0, b1, 0);

    // 6) ffn2 = F @ w2 + b2 -> fp32
    gemm_tc<3,false><<<dim3(D/BN, (B*S)/BM, 1), NTH, SMEM_SZ>>>(
        Fh, W2h, ffn2, nullptr, D, DFF, 0, 0, 0, b2, 0);

    // 7) out = LN2(h + ffn2)
    addln_kernel<true,false><<<B*S, 256>>>(h, ffn2, g2, bt2, out, nullptr, D);
}